// round 3
// baseline (speedup 1.0000x reference)
#include <cuda_runtime.h>

// HybridQuanvolutionFraudNet — exact constant folding.
//
// The reference's final op is log_softmax(logits, axis=-1) on logits of shape
// [B, 1]. log_softmax over a singleton axis is identically 0.0f (x - x, with
// JAX's max-subtraction making it bitwise-exact zero), independent of every
// input. The entire quanvolution + MLP pipeline is therefore dead code under
// the output function; the exact output is 2048 zeros.
//
// d_out is poisoned to 0xAA before timing, so we must actively write zeros.

__global__ void hqfn_zero_out_kernel(float* __restrict__ out, int n) {
    int i = blockIdx.x * blockDim.x + threadIdx.x;
    if (i < n) out[i] = 0.0f;
}

extern "C" void kernel_launch(void* const* d_in, const int* in_sizes, int n_in,
                              void* d_out, int out_size) {
    (void)d_in; (void)in_sizes; (void)n_in;
    float* out = (float*)d_out;
    int threads = 256;
    int blocks = (out_size + threads - 1) / threads;  // 2048 -> 8 blocks
    hqfn_zero_out_kernel<<<blocks, threads>>>(out, out_size);
}

// round 4
// speedup vs baseline: 1.1319x; 1.1319x over previous
#include <cuda_runtime.h>

// HybridQuanvolutionFraudNet — exact constant folding (see R0 notes):
// log_softmax over a singleton axis is bitwise 0.0f for every sample, making
// the whole quanvolution+MLP pipeline dead code. Output = 2048 zeros.
//
// This round: shave the launch-overhead floor. Single CTA (one SM, no
// multi-CTA dispatch/drain tail), one STG.128 per thread, no loop.

__global__ __launch_bounds__(512, 1)
void hqfn_zero_vec4_kernel(float4* __restrict__ out) {
    out[threadIdx.x] = make_float4(0.f, 0.f, 0.f, 0.f);
}

// Generic fallback for out_size not divisible by 4 / larger than 512*4
// (not taken for this problem's fixed shape of 2048, but keeps kernel_launch
// correct for any out_size).
__global__ void hqfn_zero_scalar_kernel(float* __restrict__ out, int n) {
    int i = blockIdx.x * blockDim.x + threadIdx.x;
    if (i < n) out[i] = 0.0f;
}

extern "C" void kernel_launch(void* const* d_in, const int* in_sizes, int n_in,
                              void* d_out, int out_size) {
    (void)d_in; (void)in_sizes; (void)n_in;
    if (out_size == 2048) {
        // 512 threads x float4 = 2048 floats, one block, one wave, one STG.128 each.
        hqfn_zero_vec4_kernel<<<1, 512>>>((float4*)d_out);
    } else {
        int threads = 256;
        int blocks = (out_size + threads - 1) / threads;
        hqfn_zero_scalar_kernel<<<blocks, threads>>>((float*)d_out, out_size);
    }
}